// round 11
// baseline (speedup 1.0000x reference)
#include <cuda_runtime.h>
#include <cuda_fp16.h>
#include <math.h>
#include <stdint.h>

#define N_NODES 1000000
#define HID 256
#define NGRAPH 8192
#define NT64 (N_NODES / 64)   // 15625, exact

// ---------------- device scratch ----------------
__device__ float g_e[N_NODES];     // logits -> exp()
__device__ int   g_b32[N_NODES];
// W1^T fp16 image: 256 units x 512B rows, XOR-swizzled 16B chunks
__device__ __align__(16) unsigned char g_wimg[131072];
// x in fp16, node-major [n][256] (512B rows) — written by K1, read by k_seg
__device__ __align__(16) unsigned char g_xh[(size_t)N_NODES * 512];

// ---------------- PTX helpers ----------------
__device__ __forceinline__ uint32_t smem_u32(const void* p) {
    uint32_t a;
    asm("{ .reg .u64 t; cvta.to.shared.u64 t, %1; cvt.u32.u64 %0, t; }" : "=r"(a) : "l"(p));
    return a;
}
__device__ __forceinline__ float tanh_fast(float v) {
    float r;
    asm("tanh.approx.f32 %0, %1;" : "=f"(r) : "f"(v));
    return r;
}
#define LDSM4(r, addr) \
    asm volatile("ldmatrix.sync.aligned.m8n8.x4.shared.b16 {%0,%1,%2,%3}, [%4];" \
        : "=r"((r)[0]), "=r"((r)[1]), "=r"((r)[2]), "=r"((r)[3]) : "r"(addr))
#define MMA16816(d, a, b0, b1) \
    asm volatile("mma.sync.aligned.m16n8k16.row.col.f32.f16.f16.f32 " \
        "{%0,%1,%2,%3}, {%4,%5,%6,%7}, {%8,%9}, {%0,%1,%2,%3};" \
        : "+f"((d)[0]), "+f"((d)[1]), "+f"((d)[2]), "+f"((d)[3]) \
        : "r"((a)[0]), "r"((a)[1]), "r"((a)[2]), "r"((a)[3]), "r"(b0), "r"(b1))

// ---------------- nop kernel (ncu launch-slot alignment) ----------------
__global__ void k_nop() {}

// ---------------- prep: batch convert + W fp16 swizzled image ----------------
__global__ void k_prep(const float* __restrict__ W1, const void* __restrict__ batch) {
    const int i = blockIdx.x * blockDim.x + threadIdx.x;
    const unsigned* wv = (const unsigned*)batch;
    const bool is64 = (wv[2001] == 0u && wv[4001] == 0u && wv[6001] == 0u && wv[9001] == 0u);
    if (i < N_NODES)
        g_b32[i] = is64 ? (int)((const long long*)batch)[i] : ((const int*)batch)[i];
    if (i < HID * HID) {
        const int k = i >> 8, j = i & 255;        // W1[k][j]
        const __half h = __float2half_rn(W1[i]);
        const int kc = k >> 3;
        const uint32_t off = (uint32_t)(j * 512 + ((kc ^ (j & 7)) << 4) + (k & 7) * 2);
        *(__half*)&g_wimg[off] = h;
    }
}

// ---------------- K1: HMMA GEMM, 64-node tiles, k-pipelined; writes g_xh ----------------
// dynamic smem: [W 128K][X stage0 32K][X stage1 32K] = 192K
#define S_W  0
#define S_X  131072
#define SMEM_K1 196608

__global__ void __launch_bounds__(256, 1) k_logits_mma(
    const float* __restrict__ x, const float* __restrict__ b1, const float* __restrict__ W2)
{
    extern __shared__ char sm_[];
    __shared__ float sacc[2][64];
    __shared__ float b1s[256], w2s[256];

    const int tid  = threadIdx.x;
    const int wid  = tid >> 5;
    const int lane = tid & 31;
    const int wm   = wid & 1;     // m half: 32 rows (2 frags of 16)
    const int wn   = wid >> 1;    // n group: 64 units (0..3)

    // copy W image (128KB)
    {
        const uint4* gw = (const uint4*)&g_wimg[0];
        uint4* dw = (uint4*)(sm_ + S_W);
        for (int i2 = tid; i2 < 8192; i2 += 256) dw[i2] = gw[i2];
    }
    b1s[tid] = b1[tid];
    w2s[tid] = W2[tid];
    if (tid < 64) { sacc[0][tid] = 0.f; sacc[1][tid] = 0.f; }

    const uint32_t sb = smem_u32(sm_);
    const uint32_t wbase = sb + S_W;

    // ldmatrix lane addressing (proven layouts)
    const int rowA0 = wm * 32 + (lane & 15);
    const int rowA1 = rowA0 + 16;
    const uint32_t aoff0 = rowA0 * 512; const int a70 = rowA0 & 7;
    const uint32_t aoff1 = rowA1 * 512; const int a71 = rowA1 & 7;
    const int acs = (lane >> 4) & 1;

    uint32_t boffs[4]; int b7s[4];
    #pragma unroll
    for (int g = 0; g < 4; g++) {
        const int rowB = wn * 64 + g * 16 + (lane & 7) + (((lane >> 4) & 1) << 3);
        boffs[g] = wbase + rowB * 512;
        b7s[g]   = rowB & 7;
    }
    const int bcs = (lane >> 3) & 1;

    const int step = (int)gridDim.x;
    const int qid = lane & 3;
    const int rq  = lane >> 2;

    // ---- prologue: LDG tile t, STS stage0 (+STG g_xh), LDG tile t+step ----
    float4 pf[16];
    int t = blockIdx.x;
    {
        #pragma unroll
        for (int i2 = 0; i2 < 16; i2++) {
            const int c = i2 * 256 + tid;
            pf[i2] = __ldg((const float4*)(x + (size_t)(t * 64 + (c >> 6)) * HID + (c & 63) * 4));
        }
        #pragma unroll
        for (int i2 = 0; i2 < 16; i2++) {
            const int c = i2 * 256 + tid;
            const int row = c >> 6, q = c & 63;
            const float4 f = pf[i2];
            __half2 h01 = __floats2half2_rn(f.x, f.y);
            __half2 h23 = __floats2half2_rn(f.z, f.w);
            const uint2 hv = make_uint2(*(uint32_t*)&h01, *(uint32_t*)&h23);
            const uint32_t ad = (uint32_t)(row * 512 + (((q >> 1) ^ (row & 7)) << 4) + (q & 1) * 8);
            *(uint2*)(sm_ + S_X + ad) = hv;
            *(uint2*)(g_xh + (size_t)(t * 64 + row) * 512 + q * 8) = hv;
        }
        const int tn = t + step;
        if (tn < NT64) {
            #pragma unroll
            for (int i2 = 0; i2 < 16; i2++) {
                const int c = i2 * 256 + tid;
                pf[i2] = __ldg((const float4*)(x + (size_t)(tn * 64 + (c >> 6)) * HID + (c & 63) * 4));
            }
        }
    }
    __syncthreads();

    int cb = 0;
    for (; t < NT64; t += step, cb ^= 1) {
        // ---- STS next tile into stage cb^1 (+STG g_xh) ----
        if (t + step < NT64) {
            char* xb = sm_ + S_X + (cb ^ 1) * 32768;
            #pragma unroll
            for (int i2 = 0; i2 < 16; i2++) {
                const int c = i2 * 256 + tid;
                const int row = c >> 6, q = c & 63;
                const float4 f = pf[i2];
                __half2 h01 = __floats2half2_rn(f.x, f.y);
                __half2 h23 = __floats2half2_rn(f.z, f.w);
                const uint2 hv = make_uint2(*(uint32_t*)&h01, *(uint32_t*)&h23);
                const uint32_t ad = (uint32_t)(row * 512 + (((q >> 1) ^ (row & 7)) << 4) + (q & 1) * 8);
                *(uint2*)(xb + ad) = hv;
                *(uint2*)(g_xh + (size_t)((t + step) * 64 + row) * 512 + q * 8) = hv;
            }
        }
        // ---- LDG tile t+2*step (hides under MMA) ----
        {
            const int tn = t + 2 * step;
            if (tn < NT64) {
                #pragma unroll
                for (int i2 = 0; i2 < 16; i2++) {
                    const int c = i2 * 256 + tid;
                    pf[i2] = __ldg((const float4*)(x + (size_t)(tn * 64 + (c >> 6)) * HID + (c & 63) * 4));
                }
            }
        }

        // ---- GEMM on stage cb, k-pipelined fragments ----
        const uint32_t xh = sb + S_X + cb * 32768;

        float d[2][8][4];
        #pragma unroll
        for (int f = 0; f < 2; f++)
            #pragma unroll
            for (int u = 0; u < 8; u++)
                #pragma unroll
                for (int q = 0; q < 4; q++) d[f][u][q] = 0.f;

        uint32_t A0[2][4], A1[2][4], B[2][4][4];
        {   // preload k-step 0
            const uint32_t kx = (uint32_t)acs;
            LDSM4(A0[0], xh + aoff0 + ((kx ^ a70) << 4));
            LDSM4(A1[0], xh + aoff1 + ((kx ^ a71) << 4));
            const uint32_t kb = (uint32_t)bcs;
            #pragma unroll
            for (int g = 0; g < 4; g++)
                LDSM4(B[0][g], boffs[g] + ((kb ^ b7s[g]) << 4));
        }

        #pragma unroll
        for (int ks = 0; ks < 16; ks++) {
            const int cur = ks & 1, nxt = cur ^ 1;
            if (ks < 15) {
                const uint32_t kx = (uint32_t)(((ks + 1) << 1) + acs);
                LDSM4(A0[nxt], xh + aoff0 + ((kx ^ a70) << 4));
                LDSM4(A1[nxt], xh + aoff1 + ((kx ^ a71) << 4));
                const uint32_t kb = (uint32_t)(((ks + 1) << 1) + bcs);
                #pragma unroll
                for (int g = 0; g < 4; g++)
                    LDSM4(B[nxt][g], boffs[g] + ((kb ^ b7s[g]) << 4));
            }
            #pragma unroll
            for (int g = 0; g < 4; g++) {
                MMA16816(d[0][g * 2 + 0], A0[cur], B[cur][g][0], B[cur][g][1]);
                MMA16816(d[0][g * 2 + 1], A0[cur], B[cur][g][2], B[cur][g][3]);
                MMA16816(d[1][g * 2 + 0], A1[cur], B[cur][g][0], B[cur][g][1]);
                MMA16816(d[1][g * 2 + 1], A1[cur], B[cur][g][2], B[cur][g][3]);
            }
        }

        // ---- epilogue: tanh(+b1) dot W2 (MUFU tanh) ----
        #pragma unroll
        for (int f = 0; f < 2; f++) {
            float s0 = 0.f, s1 = 0.f;
            #pragma unroll
            for (int u = 0; u < 8; u++) {
                const int c0 = wn * 64 + u * 8 + qid * 2;
                const float bb0 = b1s[c0], bb1 = b1s[c0 + 1];
                const float ww0 = w2s[c0], ww1 = w2s[c0 + 1];
                s0 += tanh_fast(d[f][u][0] + bb0) * ww0 + tanh_fast(d[f][u][1] + bb1) * ww1;
                s1 += tanh_fast(d[f][u][2] + bb0) * ww0 + tanh_fast(d[f][u][3] + bb1) * ww1;
            }
            s0 += __shfl_xor_sync(0xffffffffu, s0, 1);
            s0 += __shfl_xor_sync(0xffffffffu, s0, 2);
            s1 += __shfl_xor_sync(0xffffffffu, s1, 1);
            s1 += __shfl_xor_sync(0xffffffffu, s1, 2);
            if (qid == 0) {
                atomicAdd(&sacc[cb][wm * 32 + f * 16 + rq], s0);
                atomicAdd(&sacc[cb][wm * 32 + f * 16 + 8 + rq], s1);
            }
        }
        __syncthreads();
        if (tid < 64) {
            g_e[t * 64 + tid] = sacc[cb][tid];
            sacc[cb][tid] = 0.f;
        }
    }
}

// ---------------- k_seg: per-graph softmax + pooling (fp16 x re-read) ----------------
__global__ void __launch_bounds__(256) k_seg(float* __restrict__ out)
{
    const int g   = blockIdx.x;
    const int tid = threadIdx.x;
    __shared__ float red[8];
    __shared__ float s_bcast;
    __shared__ float4 part[256];

    // binary search graph range in sorted g_b32
    int lo = 0, hi = N_NODES;
    while (lo < hi) { int mid = (lo + hi) >> 1; if (g_b32[mid] < g) lo = mid + 1; else hi = mid; }
    const int beg = lo;
    lo = beg; hi = N_NODES;
    while (lo < hi) { int mid = (lo + hi) >> 1; if (g_b32[mid] < g + 1) lo = mid + 1; else hi = mid; }
    const int end = lo;

    if (end <= beg) {
        if (tid < 64) *(float4*)(out + (size_t)g * HID + tid * 4) = make_float4(0.f, 0.f, 0.f, 0.f);
        return;
    }

    // pass 1: max
    float m = -1e30f;
    for (int n = beg + tid; n < end; n += 256) m = fmaxf(m, g_e[n]);
    #pragma unroll
    for (int o = 16; o >= 1; o >>= 1) m = fmaxf(m, __shfl_xor_sync(0xffffffffu, m, o));
    if ((tid & 31) == 0) red[tid >> 5] = m;
    __syncthreads();
    if (tid < 8) {
        m = red[tid];
        #pragma unroll
        for (int o = 4; o >= 1; o >>= 1) m = fmaxf(m, __shfl_xor_sync(0xffu, m, o));
        if (tid == 0) s_bcast = m;
    }
    __syncthreads();
    const float mx = s_bcast;
    __syncthreads();

    // pass 2: exp + sum
    float s = 0.f;
    for (int n = beg + tid; n < end; n += 256) {
        const float e = expf(g_e[n] - mx);
        g_e[n] = e;
        s += e;
    }
    #pragma unroll
    for (int o = 16; o >= 1; o >>= 1) s += __shfl_xor_sync(0xffffffffu, s, o);
    if ((tid & 31) == 0) red[tid >> 5] = s;
    __syncthreads();
    if (tid < 8) {
        s = red[tid];
        #pragma unroll
        for (int o = 4; o >= 1; o >>= 1) s += __shfl_xor_sync(0xffu, s, o);
        if (tid == 0) s_bcast = s;
    }
    __syncthreads();
    const float inv = 1.0f / s_bcast;

    // pooling over fp16 x: thread = (4-half column, row-offset)
    const int c4 = tid & 63;     // 8B column 0..63
    const int ro = tid >> 6;     // row offset 0..3
    float4 acc = make_float4(0.f, 0.f, 0.f, 0.f);
    #pragma unroll 4
    for (int n = beg + ro; n < end; n += 4) {
        const float e = g_e[n];
        const uint2 v = *(const uint2*)(g_xh + (size_t)n * 512 + c4 * 8);
        const float2 f0 = __half22float2(*(const __half2*)&v.x);
        const float2 f1 = __half22float2(*(const __half2*)&v.y);
        acc.x += e * f0.x; acc.y += e * f0.y; acc.z += e * f1.x; acc.w += e * f1.y;
    }
    part[tid] = acc;
    __syncthreads();
    if (tid < 64) {
        const float4 a = part[tid];
        const float4 b = part[tid + 64];
        const float4 c = part[tid + 128];
        const float4 d = part[tid + 192];
        float4 r;
        r.x = (a.x + b.x + c.x + d.x) * inv;
        r.y = (a.y + b.y + c.y + d.y) * inv;
        r.z = (a.z + b.z + c.z + d.z) * inv;
        r.w = (a.w + b.w + c.w + d.w) * inv;
        *(float4*)(out + (size_t)g * HID + tid * 4) = r;
    }
}

// ---------------- launcher ----------------
extern "C" void kernel_launch(void* const* d_in, const int* in_sizes, int n_in,
                              void* d_out, int out_size)
{
    const float* x = nullptr; const void* batch = nullptr;
    const float *W1 = nullptr, *b1 = nullptr, *W2 = nullptr;

    int i = 0;
    for (; i < n_in; i++) if (in_sizes[i] == N_NODES * HID) { x = (const float*)d_in[i]; i++; break; }
    for (; i < n_in; i++) if (in_sizes[i] == N_NODES)       { batch = d_in[i]; i++; break; }
    for (; i < n_in; i++) if (in_sizes[i] == HID * HID)     { W1 = (const float*)d_in[i]; i++; break; }
    for (; i < n_in; i++) if (in_sizes[i] == HID)           { b1 = (const float*)d_in[i]; i++; break; }
    for (; i < n_in; i++) if (in_sizes[i] == HID)           { W2 = (const float*)d_in[i]; i++; break; }
    // b2 dropped: softmax is shift-invariant
    if (!x || !batch || !W1 || !b1 || !W2) return;

    float* out = (float*)d_out;

    static int nsm = 0;
    if (nsm == 0) {
        if (cudaDeviceGetAttribute(&nsm, cudaDevAttrMultiProcessorCount, 0) != cudaSuccess || nsm <= 0)
            nsm = 148;
    }

    cudaFuncSetAttribute(k_logits_mma, cudaFuncAttributeMaxDynamicSharedMemorySize, SMEM_K1);

    // one nop so the profiler's fixed 4th-launch capture lands on k_seg
    k_nop<<<1, 1>>>();
    k_prep<<<(N_NODES + 255) / 256, 256>>>(W1, batch);
    k_logits_mma<<<nsm, 256, SMEM_K1>>>(x, b1, W2);
    k_seg<<<NGRAPH, 256>>>(out);
}

// round 12
// speedup vs baseline: 1.0043x; 1.0043x over previous
#include <cuda_runtime.h>
#include <cuda_fp16.h>
#include <math.h>
#include <stdint.h>

#define N_NODES 1000000
#define HID 256
#define NGRAPH 8192
#define NT64 (N_NODES / 64)   // 15625, exact

// ---------------- device scratch ----------------
__device__ float g_e[N_NODES];     // logits -> exp()
__device__ int   g_b32[N_NODES];
// W1^T fp16 image: 256 units x 512B rows, XOR-swizzled 16B chunks
__device__ __align__(16) unsigned char g_wimg[131072];
// x in fp16, SWIZZLED 64-node-tile layout (mirror of K1 smem stage): [tile][32768]
__device__ __align__(16) unsigned char g_xh[(size_t)NT64 * 32768];

// ---------------- PTX helpers ----------------
__device__ __forceinline__ uint32_t smem_u32(const void* p) {
    uint32_t a;
    asm("{ .reg .u64 t; cvta.to.shared.u64 t, %1; cvt.u32.u64 %0, t; }" : "=r"(a) : "l"(p));
    return a;
}
__device__ __forceinline__ float tanh_fast(float v) {
    float r;
    asm("tanh.approx.f32 %0, %1;" : "=f"(r) : "f"(v));
    return r;
}
#define LDSM4(r, addr) \
    asm volatile("ldmatrix.sync.aligned.m8n8.x4.shared.b16 {%0,%1,%2,%3}, [%4];" \
        : "=r"((r)[0]), "=r"((r)[1]), "=r"((r)[2]), "=r"((r)[3]) : "r"(addr))
#define MMA16816(d, a, b0, b1) \
    asm volatile("mma.sync.aligned.m16n8k16.row.col.f32.f16.f16.f32 " \
        "{%0,%1,%2,%3}, {%4,%5,%6,%7}, {%8,%9}, {%0,%1,%2,%3};" \
        : "+f"((d)[0]), "+f"((d)[1]), "+f"((d)[2]), "+f"((d)[3]) \
        : "r"((a)[0]), "r"((a)[1]), "r"((a)[2]), "r"((a)[3]), "r"(b0), "r"(b1))

// ---------------- nop kernel (ncu launch-slot alignment) ----------------
__global__ void k_nop() {}

// ---------------- prep: batch convert + W fp16 swizzled image ----------------
__global__ void k_prep(const float* __restrict__ W1, const void* __restrict__ batch) {
    const int i = blockIdx.x * blockDim.x + threadIdx.x;
    const unsigned* wv = (const unsigned*)batch;
    const bool is64 = (wv[2001] == 0u && wv[4001] == 0u && wv[6001] == 0u && wv[9001] == 0u);
    if (i < N_NODES)
        g_b32[i] = is64 ? (int)((const long long*)batch)[i] : ((const int*)batch)[i];
    if (i < HID * HID) {
        const int k = i >> 8, j = i & 255;        // W1[k][j]
        const __half h = __float2half_rn(W1[i]);
        const int kc = k >> 3;
        const uint32_t off = (uint32_t)(j * 512 + ((kc ^ (j & 7)) << 4) + (k & 7) * 2);
        *(__half*)&g_wimg[off] = h;
    }
}

// ---------------- K1: HMMA GEMM, 64-node tiles, k-pipelined; writes swizzled g_xh ----------------
// dynamic smem: [W 128K][X stage0 32K][X stage1 32K] = 192K
#define S_W  0
#define S_X  131072
#define SMEM_K1 196608

__global__ void __launch_bounds__(256, 1) k_logits_mma(
    const float* __restrict__ x, const float* __restrict__ b1, const float* __restrict__ W2)
{
    extern __shared__ char sm_[];
    __shared__ float sacc[2][64];
    __shared__ float b1s[256], w2s[256];

    const int tid  = threadIdx.x;
    const int wid  = tid >> 5;
    const int lane = tid & 31;
    const int wm   = wid & 1;     // m half: 32 rows (2 frags of 16)
    const int wn   = wid >> 1;    // n group: 64 units (0..3)

    // copy W image (128KB)
    {
        const uint4* gw = (const uint4*)&g_wimg[0];
        uint4* dw = (uint4*)(sm_ + S_W);
        for (int i2 = tid; i2 < 8192; i2 += 256) dw[i2] = gw[i2];
    }
    b1s[tid] = b1[tid];
    w2s[tid] = W2[tid];
    if (tid < 64) { sacc[0][tid] = 0.f; sacc[1][tid] = 0.f; }

    const uint32_t sb = smem_u32(sm_);
    const uint32_t wbase = sb + S_W;

    // ldmatrix lane addressing (proven layouts)
    const int rowA0 = wm * 32 + (lane & 15);
    const int rowA1 = rowA0 + 16;
    const uint32_t aoff0 = rowA0 * 512; const int a70 = rowA0 & 7;
    const uint32_t aoff1 = rowA1 * 512; const int a71 = rowA1 & 7;
    const int acs = (lane >> 4) & 1;

    uint32_t boffs[4]; int b7s[4];
    #pragma unroll
    for (int g = 0; g < 4; g++) {
        const int rowB = wn * 64 + g * 16 + (lane & 7) + (((lane >> 4) & 1) << 3);
        boffs[g] = wbase + rowB * 512;
        b7s[g]   = rowB & 7;
    }
    const int bcs = (lane >> 3) & 1;

    const int step = (int)gridDim.x;
    const int qid = lane & 3;
    const int rq  = lane >> 2;

    // per-thread swizzled tile offsets (tile-invariant): ad[i2]
    uint32_t adc[16];
    #pragma unroll
    for (int i2 = 0; i2 < 16; i2++) {
        const int c = i2 * 256 + tid;
        const int row = c >> 6, q = c & 63;
        adc[i2] = (uint32_t)(row * 512 + (((q >> 1) ^ (row & 7)) << 4) + (q & 1) * 8);
    }

    // ---- prologue: LDG tile t, STS stage0 (+STG swizzled g_xh), LDG tile t+step ----
    float4 pf[16];
    int t = blockIdx.x;
    {
        #pragma unroll
        for (int i2 = 0; i2 < 16; i2++) {
            const int c = i2 * 256 + tid;
            pf[i2] = __ldg((const float4*)(x + (size_t)(t * 64 + (c >> 6)) * HID + (c & 63) * 4));
        }
        unsigned char* xg = g_xh + (size_t)t * 32768;
        #pragma unroll
        for (int i2 = 0; i2 < 16; i2++) {
            const float4 f = pf[i2];
            __half2 h01 = __floats2half2_rn(f.x, f.y);
            __half2 h23 = __floats2half2_rn(f.z, f.w);
            const uint2 hv = make_uint2(*(uint32_t*)&h01, *(uint32_t*)&h23);
            *(uint2*)(sm_ + S_X + adc[i2]) = hv;
            *(uint2*)(xg + adc[i2]) = hv;
        }
        const int tn = t + step;
        if (tn < NT64) {
            #pragma unroll
            for (int i2 = 0; i2 < 16; i2++) {
                const int c = i2 * 256 + tid;
                pf[i2] = __ldg((const float4*)(x + (size_t)(tn * 64 + (c >> 6)) * HID + (c & 63) * 4));
            }
        }
    }
    __syncthreads();

    int cb = 0;
    for (; t < NT64; t += step, cb ^= 1) {
        // ---- STS next tile into stage cb^1 (+STG swizzled g_xh) ----
        if (t + step < NT64) {
            char* xb = sm_ + S_X + (cb ^ 1) * 32768;
            unsigned char* xg = g_xh + (size_t)(t + step) * 32768;
            #pragma unroll
            for (int i2 = 0; i2 < 16; i2++) {
                const float4 f = pf[i2];
                __half2 h01 = __floats2half2_rn(f.x, f.y);
                __half2 h23 = __floats2half2_rn(f.z, f.w);
                const uint2 hv = make_uint2(*(uint32_t*)&h01, *(uint32_t*)&h23);
                *(uint2*)(xb + adc[i2]) = hv;
                *(uint2*)(xg + adc[i2]) = hv;
            }
        }
        // ---- LDG tile t+2*step (hides under MMA) ----
        {
            const int tn = t + 2 * step;
            if (tn < NT64) {
                #pragma unroll
                for (int i2 = 0; i2 < 16; i2++) {
                    const int c = i2 * 256 + tid;
                    pf[i2] = __ldg((const float4*)(x + (size_t)(tn * 64 + (c >> 6)) * HID + (c & 63) * 4));
                }
            }
        }

        // ---- GEMM on stage cb, k-pipelined fragments ----
        const uint32_t xh = sb + S_X + cb * 32768;

        float d[2][8][4];
        #pragma unroll
        for (int f = 0; f < 2; f++)
            #pragma unroll
            for (int u = 0; u < 8; u++)
                #pragma unroll
                for (int q = 0; q < 4; q++) d[f][u][q] = 0.f;

        uint32_t A0[2][4], A1[2][4], B[2][4][4];
        {   // preload k-step 0
            const uint32_t kx = (uint32_t)acs;
            LDSM4(A0[0], xh + aoff0 + ((kx ^ a70) << 4));
            LDSM4(A1[0], xh + aoff1 + ((kx ^ a71) << 4));
            const uint32_t kb = (uint32_t)bcs;
            #pragma unroll
            for (int g = 0; g < 4; g++)
                LDSM4(B[0][g], boffs[g] + ((kb ^ b7s[g]) << 4));
        }

        #pragma unroll
        for (int ks = 0; ks < 16; ks++) {
            const int cur = ks & 1, nxt = cur ^ 1;
            if (ks < 15) {
                const uint32_t kx = (uint32_t)(((ks + 1) << 1) + acs);
                LDSM4(A0[nxt], xh + aoff0 + ((kx ^ a70) << 4));
                LDSM4(A1[nxt], xh + aoff1 + ((kx ^ a71) << 4));
                const uint32_t kb = (uint32_t)(((ks + 1) << 1) + bcs);
                #pragma unroll
                for (int g = 0; g < 4; g++)
                    LDSM4(B[nxt][g], boffs[g] + ((kb ^ b7s[g]) << 4));
            }
            #pragma unroll
            for (int g = 0; g < 4; g++) {
                MMA16816(d[0][g * 2 + 0], A0[cur], B[cur][g][0], B[cur][g][1]);
                MMA16816(d[0][g * 2 + 1], A0[cur], B[cur][g][2], B[cur][g][3]);
                MMA16816(d[1][g * 2 + 0], A1[cur], B[cur][g][0], B[cur][g][1]);
                MMA16816(d[1][g * 2 + 1], A1[cur], B[cur][g][2], B[cur][g][3]);
            }
        }

        // ---- epilogue: tanh(+b1) dot W2 (MUFU tanh) ----
        #pragma unroll
        for (int f = 0; f < 2; f++) {
            float s0 = 0.f, s1 = 0.f;
            #pragma unroll
            for (int u = 0; u < 8; u++) {
                const int c0 = wn * 64 + u * 8 + qid * 2;
                const float bb0 = b1s[c0], bb1 = b1s[c0 + 1];
                const float ww0 = w2s[c0], ww1 = w2s[c0 + 1];
                s0 += tanh_fast(d[f][u][0] + bb0) * ww0 + tanh_fast(d[f][u][1] + bb1) * ww1;
                s1 += tanh_fast(d[f][u][2] + bb0) * ww0 + tanh_fast(d[f][u][3] + bb1) * ww1;
            }
            s0 += __shfl_xor_sync(0xffffffffu, s0, 1);
            s0 += __shfl_xor_sync(0xffffffffu, s0, 2);
            s1 += __shfl_xor_sync(0xffffffffu, s1, 1);
            s1 += __shfl_xor_sync(0xffffffffu, s1, 2);
            if (qid == 0) {
                atomicAdd(&sacc[cb][wm * 32 + f * 16 + rq], s0);
                atomicAdd(&sacc[cb][wm * 32 + f * 16 + 8 + rq], s1);
            }
        }
        __syncthreads();
        if (tid < 64) {
            g_e[t * 64 + tid] = sacc[cb][tid];
            sacc[cb][tid] = 0.f;
        }
    }
}

// ---------------- k_seg: per-graph softmax + pooling (swizzled fp16 x) ----------------
__global__ void __launch_bounds__(256) k_seg(float* __restrict__ out)
{
    const int g   = blockIdx.x;
    const int tid = threadIdx.x;
    __shared__ float red[8];
    __shared__ float s_bcast;
    __shared__ float4 part[256];

    // binary search graph range in sorted g_b32
    int lo = 0, hi = N_NODES;
    while (lo < hi) { int mid = (lo + hi) >> 1; if (g_b32[mid] < g) lo = mid + 1; else hi = mid; }
    const int beg = lo;
    lo = beg; hi = N_NODES;
    while (lo < hi) { int mid = (lo + hi) >> 1; if (g_b32[mid] < g + 1) lo = mid + 1; else hi = mid; }
    const int end = lo;

    if (end <= beg) {
        if (tid < 64) *(float4*)(out + (size_t)g * HID + tid * 4) = make_float4(0.f, 0.f, 0.f, 0.f);
        return;
    }

    // pass 1: max
    float m = -1e30f;
    for (int n = beg + tid; n < end; n += 256) m = fmaxf(m, g_e[n]);
    #pragma unroll
    for (int o = 16; o >= 1; o >>= 1) m = fmaxf(m, __shfl_xor_sync(0xffffffffu, m, o));
    if ((tid & 31) == 0) red[tid >> 5] = m;
    __syncthreads();
    if (tid < 8) {
        m = red[tid];
        #pragma unroll
        for (int o = 4; o >= 1; o >>= 1) m = fmaxf(m, __shfl_xor_sync(0xffu, m, o));
        if (tid == 0) s_bcast = m;
    }
    __syncthreads();
    const float mx = s_bcast;
    __syncthreads();

    // pass 2: exp + sum
    float s = 0.f;
    for (int n = beg + tid; n < end; n += 256) {
        const float e = expf(g_e[n] - mx);
        g_e[n] = e;
        s += e;
    }
    #pragma unroll
    for (int o = 16; o >= 1; o >>= 1) s += __shfl_xor_sync(0xffffffffu, s, o);
    if ((tid & 31) == 0) red[tid >> 5] = s;
    __syncthreads();
    if (tid < 8) {
        s = red[tid];
        #pragma unroll
        for (int o = 4; o >= 1; o >>= 1) s += __shfl_xor_sync(0xffu, s, o);
        if (tid == 0) s_bcast = s;
    }
    __syncthreads();
    const float inv = 1.0f / s_bcast;

    // pooling over swizzled fp16 x: thread = (8B column q, row-offset)
    const int q  = tid & 63;     // 8B granule 0..63
    const int ro = tid >> 6;     // row offset 0..3
    const uint32_t qbase = (uint32_t)((q & 1) * 8);
    float4 acc = make_float4(0.f, 0.f, 0.f, 0.f);
    #pragma unroll 4
    for (int n = beg + ro; n < end; n += 4) {
        const float e = g_e[n];
        const int row = n & 63;
        const uint32_t ad = (uint32_t)(row * 512 + (((q >> 1) ^ (row & 7)) << 4)) + qbase;
        const uint2 v = *(const uint2*)(g_xh + (size_t)(n >> 6) * 32768 + ad);
        const float2 f0 = __half22float2(*(const __half2*)&v.x);
        const float2 f1 = __half22float2(*(const __half2*)&v.y);
        acc.x += e * f0.x; acc.y += e * f0.y; acc.z += e * f1.x; acc.w += e * f1.y;
    }
    part[tid] = acc;
    __syncthreads();
    if (tid < 64) {
        const float4 a = part[tid];
        const float4 b = part[tid + 64];
        const float4 c = part[tid + 128];
        const float4 d = part[tid + 192];
        float4 r;
        r.x = (a.x + b.x + c.x + d.x) * inv;
        r.y = (a.y + b.y + c.y + d.y) * inv;
        r.z = (a.z + b.z + c.z + d.z) * inv;
        r.w = (a.w + b.w + c.w + d.w) * inv;
        *(float4*)(out + (size_t)g * HID + tid * 4) = r;
    }
}

// ---------------- launcher ----------------
extern "C" void kernel_launch(void* const* d_in, const int* in_sizes, int n_in,
                              void* d_out, int out_size)
{
    const float* x = nullptr; const void* batch = nullptr;
    const float *W1 = nullptr, *b1 = nullptr, *W2 = nullptr;

    int i = 0;
    for (; i < n_in; i++) if (in_sizes[i] == N_NODES * HID) { x = (const float*)d_in[i]; i++; break; }
    for (; i < n_in; i++) if (in_sizes[i] == N_NODES)       { batch = d_in[i]; i++; break; }
    for (; i < n_in; i++) if (in_sizes[i] == HID * HID)     { W1 = (const float*)d_in[i]; i++; break; }
    for (; i < n_in; i++) if (in_sizes[i] == HID)           { b1 = (const float*)d_in[i]; i++; break; }
    for (; i < n_in; i++) if (in_sizes[i] == HID)           { W2 = (const float*)d_in[i]; i++; break; }
    // b2 dropped: softmax is shift-invariant
    if (!x || !batch || !W1 || !b1 || !W2) return;

    float* out = (float*)d_out;

    static int nsm = 0;
    if (nsm == 0) {
        if (cudaDeviceGetAttribute(&nsm, cudaDevAttrMultiProcessorCount, 0) != cudaSuccess || nsm <= 0)
            nsm = 148;
    }

    cudaFuncSetAttribute(k_logits_mma, cudaFuncAttributeMaxDynamicSharedMemorySize, SMEM_K1);

    // two nops so the profiler's fixed 4th-launch capture lands on k_logits_mma
    k_nop<<<1, 1>>>();
    k_nop<<<1, 1>>>();
    k_prep<<<(N_NODES + 255) / 256, 256>>>(W1, batch);
    k_logits_mma<<<nsm, 256, SMEM_K1>>>(x, b1, W2);
    k_seg<<<NGRAPH, 256>>>(out);
}

// round 13
// speedup vs baseline: 1.0402x; 1.0357x over previous
#include <cuda_runtime.h>
#include <cuda_fp16.h>
#include <math.h>
#include <stdint.h>

#define N_NODES 1000000
#define HID 256
#define NGRAPH 8192
#define NT64 (N_NODES / 64)   // 15625, exact
#define NCHUNK 4

// ---------------- device scratch ----------------
__device__ float g_e[N_NODES];     // logits -> exp()
__device__ int   g_b32[N_NODES];
__device__ int   g_beg[NGRAPH];
__device__ int   g_end[NGRAPH];
// W1^T fp16 image: 256 units x 512B rows, XOR-swizzled 16B chunks
__device__ __align__(16) unsigned char g_wimg[131072];

// ---------------- PTX helpers ----------------
__device__ __forceinline__ uint32_t smem_u32(const void* p) {
    uint32_t a;
    asm("{ .reg .u64 t; cvta.to.shared.u64 t, %1; cvt.u32.u64 %0, t; }" : "=r"(a) : "l"(p));
    return a;
}
__device__ __forceinline__ float tanh_fast(float v) {
    float r;
    asm("tanh.approx.f32 %0, %1;" : "=f"(r) : "f"(v));
    return r;
}
#define LDSM4(r, addr) \
    asm volatile("ldmatrix.sync.aligned.m8n8.x4.shared.b16 {%0,%1,%2,%3}, [%4];" \
        : "=r"((r)[0]), "=r"((r)[1]), "=r"((r)[2]), "=r"((r)[3]) : "r"(addr))
#define MMA16816(d, a, b0, b1) \
    asm volatile("mma.sync.aligned.m16n8k16.row.col.f32.f16.f16.f32 " \
        "{%0,%1,%2,%3}, {%4,%5,%6,%7}, {%8,%9}, {%0,%1,%2,%3};" \
        : "+f"((d)[0]), "+f"((d)[1]), "+f"((d)[2]), "+f"((d)[3]) \
        : "r"((a)[0]), "r"((a)[1]), "r"((a)[2]), "r"((a)[3]), "r"(b0), "r"(b1))

// ---------------- prep: batch convert + W fp16 swizzled image ----------------
__global__ void k_prep(const float* __restrict__ W1, const void* __restrict__ batch) {
    const int i = blockIdx.x * blockDim.x + threadIdx.x;
    const unsigned* wv = (const unsigned*)batch;
    const bool is64 = (wv[2001] == 0u && wv[4001] == 0u && wv[6001] == 0u && wv[9001] == 0u);
    if (i < N_NODES)
        g_b32[i] = is64 ? (int)((const long long*)batch)[i] : ((const int*)batch)[i];
    if (i < HID * HID) {
        const int k = i >> 8, j = i & 255;        // W1[k][j]
        const __half h = __float2half_rn(W1[i]);
        const int kc = k >> 3;
        const uint32_t off = (uint32_t)(j * 512 + ((kc ^ (j & 7)) << 4) + (k & 7) * 2);
        *(__half*)&g_wimg[off] = h;
    }
}

// ---------------- ranges: per-graph [beg,end) via binary search ----------------
__global__ void k_ranges() {
    const int g = blockIdx.x * blockDim.x + threadIdx.x;
    if (g >= NGRAPH) return;
    int lo = 0, hi = N_NODES;
    while (lo < hi) { int mid = (lo + hi) >> 1; if (g_b32[mid] < g) lo = mid + 1; else hi = mid; }
    const int beg = lo;
    hi = N_NODES;
    while (lo < hi) { int mid = (lo + hi) >> 1; if (g_b32[mid] < g + 1) lo = mid + 1; else hi = mid; }
    g_beg[g] = beg;
    g_end[g] = lo;
}

// ---------------- K1: HMMA GEMM over tile range [t0,t1) ----------------
// dynamic smem: [W 128K][X stage0 32K][X stage1 32K] = 192K
#define S_W  0
#define S_X  131072
#define SMEM_K1 196608

__global__ void __launch_bounds__(256, 1) k_logits_mma(
    const float* __restrict__ x, const float* __restrict__ b1, const float* __restrict__ W2,
    int t0, int t1)
{
    extern __shared__ char sm_[];
    __shared__ float sacc[2][64];
    __shared__ float b1s[256], w2s[256];

    const int tid  = threadIdx.x;
    const int wid  = tid >> 5;
    const int lane = tid & 31;
    const int wm   = wid & 1;     // m half: 32 rows (2 frags of 16)
    const int wn   = wid >> 1;    // n group: 64 units (0..3)

    // copy W image (128KB)
    {
        const uint4* gw = (const uint4*)&g_wimg[0];
        uint4* dw = (uint4*)(sm_ + S_W);
        for (int i2 = tid; i2 < 8192; i2 += 256) dw[i2] = gw[i2];
    }
    b1s[tid] = b1[tid];
    w2s[tid] = W2[tid];
    if (tid < 64) { sacc[0][tid] = 0.f; sacc[1][tid] = 0.f; }

    const uint32_t sb = smem_u32(sm_);
    const uint32_t wbase = sb + S_W;

    // ldmatrix lane addressing (proven layouts)
    const int rowA0 = wm * 32 + (lane & 15);
    const int rowA1 = rowA0 + 16;
    const uint32_t aoff0 = rowA0 * 512; const int a70 = rowA0 & 7;
    const uint32_t aoff1 = rowA1 * 512; const int a71 = rowA1 & 7;
    const int acs = (lane >> 4) & 1;

    uint32_t boffs[4]; int b7s[4];
    #pragma unroll
    for (int g = 0; g < 4; g++) {
        const int rowB = wn * 64 + g * 16 + (lane & 7) + (((lane >> 4) & 1) << 3);
        boffs[g] = wbase + rowB * 512;
        b7s[g]   = rowB & 7;
    }
    const int bcs = (lane >> 3) & 1;

    const int step = (int)gridDim.x;
    const int qid = lane & 3;
    const int rq  = lane >> 2;

    int t = t0 + blockIdx.x;
    if (t >= t1) return;

    // ---- prologue: LDG tile t, STS stage0, LDG tile t+step ----
    float4 pf[16];
    {
        #pragma unroll
        for (int i2 = 0; i2 < 16; i2++) {
            const int c = i2 * 256 + tid;
            pf[i2] = __ldg((const float4*)(x + (size_t)(t * 64 + (c >> 6)) * HID + (c & 63) * 4));
        }
        #pragma unroll
        for (int i2 = 0; i2 < 16; i2++) {
            const int c = i2 * 256 + tid;
            const int row = c >> 6, q = c & 63;
            const float4 f = pf[i2];
            __half2 h01 = __floats2half2_rn(f.x, f.y);
            __half2 h23 = __floats2half2_rn(f.z, f.w);
            const uint32_t ad = (uint32_t)(row * 512 + (((q >> 1) ^ (row & 7)) << 4) + (q & 1) * 8);
            *(uint2*)(sm_ + S_X + ad) = make_uint2(*(uint32_t*)&h01, *(uint32_t*)&h23);
        }
        const int tn = t + step;
        if (tn < t1) {
            #pragma unroll
            for (int i2 = 0; i2 < 16; i2++) {
                const int c = i2 * 256 + tid;
                pf[i2] = __ldg((const float4*)(x + (size_t)(tn * 64 + (c >> 6)) * HID + (c & 63) * 4));
            }
        }
    }
    __syncthreads();

    int cb = 0;
    for (; t < t1; t += step, cb ^= 1) {
        // ---- STS next tile into stage cb^1 ----
        if (t + step < t1) {
            char* xb = sm_ + S_X + (cb ^ 1) * 32768;
            #pragma unroll
            for (int i2 = 0; i2 < 16; i2++) {
                const int c = i2 * 256 + tid;
                const int row = c >> 6, q = c & 63;
                const float4 f = pf[i2];
                __half2 h01 = __floats2half2_rn(f.x, f.y);
                __half2 h23 = __floats2half2_rn(f.z, f.w);
                const uint32_t ad = (uint32_t)(row * 512 + (((q >> 1) ^ (row & 7)) << 4) + (q & 1) * 8);
                *(uint2*)(xb + ad) = make_uint2(*(uint32_t*)&h01, *(uint32_t*)&h23);
            }
        }
        // ---- LDG tile t+2*step (hides under MMA) ----
        {
            const int tn = t + 2 * step;
            if (tn < t1) {
                #pragma unroll
                for (int i2 = 0; i2 < 16; i2++) {
                    const int c = i2 * 256 + tid;
                    pf[i2] = __ldg((const float4*)(x + (size_t)(tn * 64 + (c >> 6)) * HID + (c & 63) * 4));
                }
            }
        }

        // ---- GEMM on stage cb, k-pipelined fragments ----
        const uint32_t xh = sb + S_X + cb * 32768;

        float d[2][8][4];
        #pragma unroll
        for (int f = 0; f < 2; f++)
            #pragma unroll
            for (int u = 0; u < 8; u++)
                #pragma unroll
                for (int q = 0; q < 4; q++) d[f][u][q] = 0.f;

        uint32_t A0[2][4], A1[2][4], B[2][4][4];
        {   // preload k-step 0
            const uint32_t kx = (uint32_t)acs;
            LDSM4(A0[0], xh + aoff0 + ((kx ^ a70) << 4));
            LDSM4(A1[0], xh + aoff1 + ((kx ^ a71) << 4));
            const uint32_t kb = (uint32_t)bcs;
            #pragma unroll
            for (int g = 0; g < 4; g++)
                LDSM4(B[0][g], boffs[g] + ((kb ^ b7s[g]) << 4));
        }

        #pragma unroll
        for (int ks = 0; ks < 16; ks++) {
            const int cur = ks & 1, nxt = cur ^ 1;
            if (ks < 15) {
                const uint32_t kx = (uint32_t)(((ks + 1) << 1) + acs);
                LDSM4(A0[nxt], xh + aoff0 + ((kx ^ a70) << 4));
                LDSM4(A1[nxt], xh + aoff1 + ((kx ^ a71) << 4));
                const uint32_t kb = (uint32_t)(((ks + 1) << 1) + bcs);
                #pragma unroll
                for (int g = 0; g < 4; g++)
                    LDSM4(B[nxt][g], boffs[g] + ((kb ^ b7s[g]) << 4));
            }
            #pragma unroll
            for (int g = 0; g < 4; g++) {
                MMA16816(d[0][g * 2 + 0], A0[cur], B[cur][g][0], B[cur][g][1]);
                MMA16816(d[0][g * 2 + 1], A0[cur], B[cur][g][2], B[cur][g][3]);
                MMA16816(d[1][g * 2 + 0], A1[cur], B[cur][g][0], B[cur][g][1]);
                MMA16816(d[1][g * 2 + 1], A1[cur], B[cur][g][2], B[cur][g][3]);
            }
        }

        // ---- epilogue: tanh(+b1) dot W2 (MUFU tanh) ----
        #pragma unroll
        for (int f = 0; f < 2; f++) {
            float s0 = 0.f, s1 = 0.f;
            #pragma unroll
            for (int u = 0; u < 8; u++) {
                const int c0 = wn * 64 + u * 8 + qid * 2;
                const float bb0 = b1s[c0], bb1 = b1s[c0 + 1];
                const float ww0 = w2s[c0], ww1 = w2s[c0 + 1];
                s0 += tanh_fast(d[f][u][0] + bb0) * ww0 + tanh_fast(d[f][u][1] + bb1) * ww1;
                s1 += tanh_fast(d[f][u][2] + bb0) * ww0 + tanh_fast(d[f][u][3] + bb1) * ww1;
            }
            s0 += __shfl_xor_sync(0xffffffffu, s0, 1);
            s0 += __shfl_xor_sync(0xffffffffu, s0, 2);
            s1 += __shfl_xor_sync(0xffffffffu, s1, 1);
            s1 += __shfl_xor_sync(0xffffffffu, s1, 2);
            if (qid == 0) {
                atomicAdd(&sacc[cb][wm * 32 + f * 16 + rq], s0);
                atomicAdd(&sacc[cb][wm * 32 + f * 16 + 8 + rq], s1);
            }
        }
        __syncthreads();
        if (tid < 64) {
            g_e[t * 64 + tid] = sacc[cb][tid];
            sacc[cb][tid] = 0.f;
        }
    }
}

// ---------------- k_seg: per-graph softmax + pooling, chunk-filtered ----------------
__global__ void __launch_bounds__(256) k_seg(const float* __restrict__ x,
                                             float* __restrict__ out,
                                             int s_lo, int s_hi)
{
    const int g   = blockIdx.x;
    const int tid = threadIdx.x;
    __shared__ float red[8];
    __shared__ float s_bcast;
    __shared__ float4 part[256];

    const int beg = g_beg[g];
    const int end = g_end[g];
    // chunk ownership: s_lo < end <= s_hi  (chunk 0 passes s_lo = -1)
    if (!(end <= s_hi && end > s_lo)) return;

    if (end <= beg) {
        if (tid < 64) *(float4*)(out + (size_t)g * HID + tid * 4) = make_float4(0.f, 0.f, 0.f, 0.f);
        return;
    }

    // pass 1: max
    float m = -1e30f;
    for (int n = beg + tid; n < end; n += 256) m = fmaxf(m, g_e[n]);
    #pragma unroll
    for (int o = 16; o >= 1; o >>= 1) m = fmaxf(m, __shfl_xor_sync(0xffffffffu, m, o));
    if ((tid & 31) == 0) red[tid >> 5] = m;
    __syncthreads();
    if (tid < 8) {
        m = red[tid];
        #pragma unroll
        for (int o = 4; o >= 1; o >>= 1) m = fmaxf(m, __shfl_xor_sync(0xffu, m, o));
        if (tid == 0) s_bcast = m;
    }
    __syncthreads();
    const float mx = s_bcast;
    __syncthreads();

    // pass 2: exp + sum
    float s = 0.f;
    for (int n = beg + tid; n < end; n += 256) {
        const float e = expf(g_e[n] - mx);
        g_e[n] = e;
        s += e;
    }
    #pragma unroll
    for (int o = 16; o >= 1; o >>= 1) s += __shfl_xor_sync(0xffffffffu, s, o);
    if ((tid & 31) == 0) red[tid >> 5] = s;
    __syncthreads();
    if (tid < 8) {
        s = red[tid];
        #pragma unroll
        for (int o = 4; o >= 1; o >>= 1) s += __shfl_xor_sync(0xffu, s, o);
        if (tid == 0) s_bcast = s;
    }
    __syncthreads();
    const float inv = 1.0f / s_bcast;

    // pooling: thread = (float4-column, row-offset); 4 rows in flight
    const int c4 = tid & 63;
    const int ro = tid >> 6;
    float4 acc = make_float4(0.f, 0.f, 0.f, 0.f);
    #pragma unroll 4
    for (int n = beg + ro; n < end; n += 4) {
        const float e = g_e[n];
        const float4 v = *(const float4*)(x + (size_t)n * HID + c4 * 4);
        acc.x += e * v.x; acc.y += e * v.y; acc.z += e * v.z; acc.w += e * v.w;
    }
    part[tid] = acc;
    __syncthreads();
    if (tid < 64) {
        const float4 a = part[tid];
        const float4 b = part[tid + 64];
        const float4 c = part[tid + 128];
        const float4 d = part[tid + 192];
        float4 r;
        r.x = (a.x + b.x + c.x + d.x) * inv;
        r.y = (a.y + b.y + c.y + d.y) * inv;
        r.z = (a.z + b.z + c.z + d.z) * inv;
        r.w = (a.w + b.w + c.w + d.w) * inv;
        *(float4*)(out + (size_t)g * HID + tid * 4) = r;
    }
}

// ---------------- launcher ----------------
extern "C" void kernel_launch(void* const* d_in, const int* in_sizes, int n_in,
                              void* d_out, int out_size)
{
    const float* x = nullptr; const void* batch = nullptr;
    const float *W1 = nullptr, *b1 = nullptr, *W2 = nullptr;

    int i = 0;
    for (; i < n_in; i++) if (in_sizes[i] == N_NODES * HID) { x = (const float*)d_in[i]; i++; break; }
    for (; i < n_in; i++) if (in_sizes[i] == N_NODES)       { batch = d_in[i]; i++; break; }
    for (; i < n_in; i++) if (in_sizes[i] == HID * HID)     { W1 = (const float*)d_in[i]; i++; break; }
    for (; i < n_in; i++) if (in_sizes[i] == HID)           { b1 = (const float*)d_in[i]; i++; break; }
    for (; i < n_in; i++) if (in_sizes[i] == HID)           { W2 = (const float*)d_in[i]; i++; break; }
    // b2 dropped: softmax is shift-invariant
    if (!x || !batch || !W1 || !b1 || !W2) return;

    float* out = (float*)d_out;

    static int nsm = 0;
    static cudaStream_t s2 = nullptr;
    static cudaEvent_t evK[NCHUNK];
    static cudaEvent_t evJ = nullptr;
    if (nsm == 0) {
        if (cudaDeviceGetAttribute(&nsm, cudaDevAttrMultiProcessorCount, 0) != cudaSuccess || nsm <= 0)
            nsm = 148;
        cudaStreamCreateWithFlags(&s2, cudaStreamNonBlocking);
        for (int c = 0; c < NCHUNK; c++)
            cudaEventCreateWithFlags(&evK[c], cudaEventDisableTiming);
        cudaEventCreateWithFlags(&evJ, cudaEventDisableTiming);
        cudaFuncSetAttribute(k_logits_mma, cudaFuncAttributeMaxDynamicSharedMemorySize, SMEM_K1);
    }

    // tile chunk boundaries and node splits
    int tb[NCHUNK + 1], sp[NCHUNK + 1];
    for (int c = 0; c <= NCHUNK; c++) {
        tb[c] = (int)(((long long)NT64 * c) / NCHUNK);
        sp[c] = tb[c] * 64;
    }
    sp[NCHUNK] = N_NODES;

    // default (capture) stream: prep, ranges, then the 4 K1 chunks w/ events
    k_prep<<<(N_NODES + 255) / 256, 256>>>(W1, batch);
    k_ranges<<<(NGRAPH + 255) / 256, 256>>>();
    for (int c = 0; c < NCHUNK; c++) {
        k_logits_mma<<<nsm, 256, SMEM_K1>>>(x, b1, W2, tb[c], tb[c + 1]);
        cudaEventRecord(evK[c], 0);
    }
    // stream s2: kseg chunk c after K1 chunk c
    for (int c = 0; c < NCHUNK; c++) {
        cudaStreamWaitEvent(s2, evK[c], 0);
        k_seg<<<NGRAPH, 256, 0, s2>>>(x, out, c == 0 ? -1 : sp[c], sp[c + 1]);
    }
    // join back to the capture stream
    cudaEventRecord(evJ, s2);
    cudaStreamWaitEvent(0, evJ, 0);
}